// round 10
// baseline (speedup 1.0000x reference)
#include <cuda_runtime.h>
#include <cstdint>

#define E_ 100
#define V_ 3
#define S_ 100
#define T_ 10
#define B_ 8192
#define NT 256

// Precomputed folded weights / transposed fc1_w (computed once per launch)
__device__ float4 g_w2v[75];        // w2[v][j] folded, float4-aligned
__device__ float  g_w3[V_ * E_];
__device__ float  g_c[V_];
__device__ float  g_c2[V_];
__device__ float  g_fc1T[E_ * E_];  // fc1T[e][i] = fc1_w[i][e]

__global__ void mvke_pre(const float* __restrict__ vk,
                         const float* __restrict__ fc1_w, const float* __restrict__ fc1_b,
                         const float* __restrict__ fc2_w, const float* __restrict__ fc2_b,
                         const float* __restrict__ fc3_w, const float* __restrict__ fc3_b,
                         const float* __restrict__ fc4_w, const float* __restrict__ fc4_b)
{
    __shared__ float of2[V_][E_];
    __shared__ float of3[V_][E_];
    const int tid = threadIdx.x;

    for (int idx = tid; idx < V_ * E_; idx += blockDim.x) {
        int v = idx / E_, e = idx % E_;
        float s2 = fc2_b[e], s3 = fc3_b[e];
        for (int j = 0; j < E_; j++) {
            float vv = vk[v * E_ + j];
            s2 += fc2_w[e * E_ + j] * vv;
            s3 += fc3_w[e * E_ + j] * vv;
        }
        of2[v][e] = s2;
        of3[v][e] = s3;
    }
    __syncthreads();

    for (int idx = tid; idx < V_ * E_; idx += blockDim.x) {
        int v = idx / E_, j = idx % E_;
        float s2 = 0.f, s3 = 0.f;
        for (int e = 0; e < E_; e++) {
            s2 += of2[v][e] * fc1_w[e * E_ + j];
            s3 += of3[v][e] * fc4_w[e * E_ + j];
        }
        ((float*)g_w2v)[idx] = s2;
        g_w3[idx] = s3;
    }
    for (int idx = tid; idx < E_ * E_; idx += blockDim.x) {
        int i = idx / E_, e = idx % E_;
        g_fc1T[e * E_ + i] = fc1_w[i * E_ + e];
    }
    if (tid < V_) {
        float s = 0.f, s2 = 0.f;
        for (int e = 0; e < E_; e++) {
            s  += of2[tid][e] * fc1_b[e];
            s2 += of3[tid][e] * fc4_b[e];
        }
        g_c[tid]  = s;
        g_c2[tid] = s2;
    }
}

__device__ __forceinline__ float dot4(float4 a, float4 b) {
    return a.x * b.x + a.y * b.y + a.z * b.z + a.w * b.w;
}

__global__ __launch_bounds__(NT, 4) void mvke_main(
    const float* __restrict__ x, const float* __restrict__ tag,
    const float* __restrict__ fc1_b,
    float* __restrict__ out)
{
    __shared__ __align__(16) float xs[S_ * E_];   // 40000 B; rows 0..9 reused for tag after C
    __shared__ __align__(16) float w3s[V_ * E_];
    __shared__ __align__(16) float ys[V_ * E_];
    __shared__ __align__(16) float wB[V_ * E_];   // raw m1 -> sm1 -> ws1
    __shared__ __align__(16) float pb[V_ * E_];   // split-K partials (C, D)
    __shared__ float sas0[S_];
    __shared__ float sbuf[60];                    // m2[0..29], d[30..59]
    __shared__ float cs[V_], c2s[V_];

    float4* xs4  = (float4*)xs;
    float4* wB4  = (float4*)wB;
    float4* ys4  = (float4*)ys;
    float4* w3s4 = (float4*)w3s;

    const int b    = blockIdx.x;
    const int tid  = threadIdx.x;
    const int w    = tid >> 5;
    const int lane = tid & 31;
    const int g    = tid >> 7;       // warpgroup half for split-K phases
    const int idx  = tid & 127;
    const float scale = 0.1f;                 // 1/sqrt(DK)
    const float PAD   = -4294967296.0f;       // float32(-(2^32)+1)

    // per-lane w2 chunks in registers (lane q owns e in [4q, 4q+4))
    float4 rw0 = make_float4(0.f, 0.f, 0.f, 0.f), rw1 = rw0, rw2 = rw0;
    if (lane < 25) {
        rw0 = g_w2v[lane];
        rw1 = g_w2v[25 + lane];
        rw2 = g_w2v[50 + lane];
    }
    for (int i = tid; i < V_ * E_; i += NT) w3s[i] = g_w3[i];
    if (tid < V_) { cs[tid] = g_c[tid]; c2s[tid] = g_c2[tid]; }

    // ---- Phase A: warp-per-row. Load x row from GLOBAL (coalesced float4),
    // stash to smem for Phase C, dot against register-resident w2, butterfly-reduce.
    const float4* xg = (const float4*)(x + (size_t)b * (S_ * E_));
    #pragma unroll 2
    for (int s = w; s < S_; s += 8) {
        float4 xq = make_float4(0.f, 0.f, 0.f, 0.f);
        if (lane < 25) xq = xg[s * 25 + lane];
        if (lane < 25) xs4[s * 25 + lane] = xq;
        float d0 = dot4(xq, rw0);
        float d1 = dot4(xq, rw1);
        float d2 = dot4(xq, rw2);
        float sa = fabsf(xq.x) + fabsf(xq.y) + fabsf(xq.z) + fabsf(xq.w);
        #pragma unroll
        for (int off = 16; off; off >>= 1) {
            d0 += __shfl_xor_sync(0xffffffffu, d0, off);
            d1 += __shfl_xor_sync(0xffffffffu, d1, off);
            d2 += __shfl_xor_sync(0xffffffffu, d2, off);
            sa += __shfl_xor_sync(0xffffffffu, sa, off);
        }
        if (lane == 0) {
            wB[s] = d0; wB[100 + s] = d1; wB[200 + s] = d2; sas0[s] = sa;
        }
    }
    __syncthreads();

    // ---- Phase B: mask + scale + softmax over S per v (warp v)
    if (w < V_) {
        const int v = w;
        float vals[4];
        float mx = -3.4e38f;
        #pragma unroll
        for (int i = 0; i < 4; i++) {
            int s = lane + 32 * i;
            if (s < S_) {
                float raw = wB[v * 100 + s];
                vals[i] = (sas0[s] == 0.0f) ? PAD : scale * (raw + cs[v]);
            } else vals[i] = -3.4e38f;
            mx = fmaxf(mx, vals[i]);
        }
        #pragma unroll
        for (int off = 16; off; off >>= 1)
            mx = fmaxf(mx, __shfl_xor_sync(0xffffffffu, mx, off));
        float sum = 0.f;
        #pragma unroll
        for (int i = 0; i < 4; i++) {
            int s = lane + 32 * i;
            vals[i] = expf(vals[i] - mx);
            if (s < S_) sum += vals[i];
        }
        #pragma unroll
        for (int off = 16; off; off >>= 1)
            sum += __shfl_xor_sync(0xffffffffu, sum, off);
        float inv = 1.0f / sum;
        #pragma unroll
        for (int i = 0; i < 4; i++) {
            int s = lane + 32 * i;
            if (s < S_) wB[v * 100 + s] = vals[i] * inv;   // final sm1
        }
    }
    __syncthreads();

    // ---- Phase C: ys halves. thread-per-e, 3 v-accums, float4 over s (smem).
    if (idx < E_) {
        const int e = idx;
        const int q0 = g ? 13 : 0, q1 = g ? 25 : 13;
        float a0 = 0.f, a1 = 0.f, a2 = 0.f;
        #pragma unroll 4
        for (int q = q0; q < q1; q++) {
            float4 p0 = wB4[q];
            float4 p1 = wB4[25 + q];
            float4 p2 = wB4[50 + q];
            const float* xc = xs + (4 * q) * E_ + e;
            float x0 = xc[0];
            float x1 = xc[E_];
            float x2 = xc[2 * E_];
            float x3 = xc[3 * E_];
            a0 += p0.x * x0 + p0.y * x1 + p0.z * x2 + p0.w * x3;
            a1 += p1.x * x0 + p1.y * x1 + p1.z * x2 + p1.w * x3;
            a2 += p2.x * x0 + p2.y * x1 + p2.z * x2 + p2.w * x3;
        }
        if (!g) { ys[e] = a0; ys[100 + e] = a1; ys[200 + e] = a2; }
        else    { pb[e] = a0; pb[100 + e] = a1; pb[200 + e] = a2; }
    }
    __syncthreads();
    for (int i = tid; i < V_ * E_; i += NT) ys[i] += pb[i];
    __syncthreads();

    // ---- Phase D: ws1 halves. thread-per-i, float4 over e, coalesced L1/L2-hot fc1T.
    if (idx < E_) {
        const int i = idx;
        const int q0 = g ? 13 : 0, q1 = g ? 25 : 13;
        float a0 = 0.f, a1 = 0.f, a2 = 0.f;
        #pragma unroll 4
        for (int q = q0; q < q1; q++) {
            float4 y0 = ys4[q];
            float4 y1 = ys4[25 + q];
            float4 y2 = ys4[50 + q];
            const float* fp = g_fc1T + (4 * q) * E_ + i;
            float f0 = fp[0];
            float f1 = fp[E_];
            float f2 = fp[2 * E_];
            float f3 = fp[3 * E_];
            a0 += f0 * y0.x + f1 * y0.y + f2 * y0.z + f3 * y0.w;
            a1 += f0 * y1.x + f1 * y1.y + f2 * y1.z + f3 * y1.w;
            a2 += f0 * y2.x + f1 * y2.y + f2 * y2.z + f3 * y2.w;
        }
        if (!g) { wB[i] = a0; wB[100 + i] = a1; wB[200 + i] = a2; }
        else    { pb[i] = a0; pb[100 + i] = a1; pb[200 + i] = a2; }
    } else {
        // 56 idle threads stage tag[b] into xs[0..999] (x data dead after C)
        const float4* tg = (const float4*)(tag + (size_t)b * (T_ * E_));
        int j = g * 28 + (idx - 100);
        for (int i4 = j; i4 < (T_ * E_) / 4; i4 += 56)
            xs4[i4] = tg[i4];
    }
    __syncthreads();
    for (int i = tid; i < V_ * E_; i += NT)
        wB[i] = wB[i] + pb[i] + fc1_b[i % E_];   // final ws1
    __syncthreads();

    // ---- Phase E: m2[t][v], d[t][v]; thread-per-(t,v), float4 over e (smem only)
    if (tid < T_ * V_) {
        const int t = tid / V_, v = tid % V_;
        float am = 0.f, ad = 0.f;
        #pragma unroll 5
        for (int i = 0; i < 25; i++) {
            float4 tq = xs4[t * 25 + i];
            float4 wq = w3s4[v * 25 + i];
            float4 uq = wB4[v * 25 + i];
            am += dot4(tq, wq);
            ad += dot4(tq, uq);
        }
        sbuf[tid]      = scale * (am + c2s[v]);  // m2
        sbuf[30 + tid] = ad;                     // d
    }
    __syncthreads();

    // ---- Phase F: softmax over T per v, then out
    if (tid < V_) {
        const int v = tid;
        float mx = sbuf[v];
        #pragma unroll
        for (int t = 1; t < T_; t++) mx = fmaxf(mx, sbuf[t * V_ + v]);
        float ev[T_];
        float sum = 0.f;
        #pragma unroll
        for (int t = 0; t < T_; t++) { ev[t] = expf(sbuf[t * V_ + v] - mx); sum += ev[t]; }
        float inv = 1.0f / sum;
        #pragma unroll
        for (int t = 0; t < T_; t++) sbuf[t * V_ + v] = ev[t] * inv;
    }
    __syncthreads();
    if (tid < T_) {
        const int t = tid;
        out[(size_t)b * T_ + t] =
            sbuf[t * V_ + 0] * sbuf[30 + t * V_ + 0] +
            sbuf[t * V_ + 1] * sbuf[30 + t * V_ + 1] +
            sbuf[t * V_ + 2] * sbuf[30 + t * V_ + 2];
    }
}

extern "C" void kernel_launch(void* const* d_in, const int* in_sizes, int n_in,
                              void* d_out, int out_size)
{
    const float* x     = (const float*)d_in[0];
    const float* tag   = (const float*)d_in[1];
    const float* vk    = (const float*)d_in[2];
    const float* fc1_w = (const float*)d_in[3];
    const float* fc1_b = (const float*)d_in[4];
    const float* fc2_w = (const float*)d_in[5];
    const float* fc2_b = (const float*)d_in[6];
    const float* fc3_w = (const float*)d_in[7];
    const float* fc3_b = (const float*)d_in[8];
    const float* fc4_w = (const float*)d_in[9];
    const float* fc4_b = (const float*)d_in[10];
    float* out = (float*)d_out;

    mvke_pre<<<1, 384>>>(vk, fc1_w, fc1_b, fc2_w, fc2_b, fc3_w, fc3_b, fc4_w, fc4_b);
    mvke_main<<<B_, NT>>>(x, tag, fc1_b, out);
}

// round 15
// speedup vs baseline: 1.4052x; 1.4052x over previous
#include <cuda_runtime.h>
#include <cstdint>

#define E_ 100
#define V_ 3
#define S_ 100
#define T_ 10
#define B_ 8192
#define NT 512

#define XB (S_ * E_ * 4)   // 40000 bytes of x per batch
#define TB (T_ * E_ * 4)   // 4000 bytes of tag per batch

// shared-between-streams region (float offsets)
#define OW2   0
#define OW3   304
#define OC    608
#define OC2   612
#define PSBASE 616
// per-stream region (float offsets from stream base)
#define PX    0        // x: 100x100 unpadded (stride 100 % 32 == 4 -> conflict-free)
#define PT0   10000    // tag buffer 0
#define PT1   11000    // tag buffer 1
#define PYS   12000
#define PWB   12300    // raw m1 -> sm1 -> ws1
#define PPB   12600    // split-K partials
#define PSAS0 12900
#define PSAS1 13000
#define PSB   13100    // m2[0..29], d[30..59]
#define PMB   13160    // mbarrier (u64)
#define SS    13164
#define SMEM_FLOATS (PSBASE + 2 * SS)
#define SMEM_BYTES  (SMEM_FLOATS * 4)

__device__ float g_w2[V_ * E_];
__device__ float g_w3[V_ * E_];
__device__ float g_c[V_];
__device__ float g_c2[V_];
__device__ float g_fc1T[E_ * E_];   // fc1T[e][i] = fc1_w[i][e]

__global__ void mvke_pre(const float* __restrict__ vk,
                         const float* __restrict__ fc1_w, const float* __restrict__ fc1_b,
                         const float* __restrict__ fc2_w, const float* __restrict__ fc2_b,
                         const float* __restrict__ fc3_w, const float* __restrict__ fc3_b,
                         const float* __restrict__ fc4_w, const float* __restrict__ fc4_b)
{
    __shared__ float of2[V_][E_];
    __shared__ float of3[V_][E_];
    const int tid = threadIdx.x;

    for (int idx = tid; idx < V_ * E_; idx += blockDim.x) {
        int v = idx / E_, e = idx % E_;
        float s2 = fc2_b[e], s3 = fc3_b[e];
        for (int j = 0; j < E_; j++) {
            float vv = vk[v * E_ + j];
            s2 += fc2_w[e * E_ + j] * vv;
            s3 += fc3_w[e * E_ + j] * vv;
        }
        of2[v][e] = s2;
        of3[v][e] = s3;
    }
    __syncthreads();

    for (int idx = tid; idx < V_ * E_; idx += blockDim.x) {
        int v = idx / E_, j = idx % E_;
        float s2 = 0.f, s3 = 0.f;
        for (int e = 0; e < E_; e++) {
            s2 += of2[v][e] * fc1_w[e * E_ + j];
            s3 += of3[v][e] * fc4_w[e * E_ + j];
        }
        g_w2[idx] = s2;
        g_w3[idx] = s3;
    }
    for (int idx = tid; idx < E_ * E_; idx += blockDim.x) {
        int i = idx / E_, e = idx % E_;
        g_fc1T[e * E_ + i] = fc1_w[i * E_ + e];
    }
    if (tid < V_) {
        float s = 0.f, s2 = 0.f;
        for (int e = 0; e < E_; e++) {
            s  += of2[tid][e] * fc1_b[e];
            s2 += of3[tid][e] * fc4_b[e];
        }
        g_c[tid]  = s;
        g_c2[tid] = s2;
    }
}

__device__ __forceinline__ float dot4(float4 a, float4 b) {
    return a.x * b.x + a.y * b.y + a.z * b.z + a.w * b.w;
}
__device__ __forceinline__ uint32_t smem_u32(const void* p) {
    uint32_t a;
    asm("{ .reg .u64 t; cvta.to.shared.u64 t, %1; cvt.u32.u64 %0, t; }" : "=r"(a) : "l"(p));
    return a;
}
__device__ __forceinline__ void mbar_init(uint32_t m) {
    asm volatile("mbarrier.init.shared.b64 [%0], 1;" :: "r"(m) : "memory");
}
__device__ __forceinline__ void issue_batch(uint32_t m, uint32_t xdst, uint32_t tdst,
                                            const float* xsrc, const float* tsrc) {
    asm volatile("mbarrier.arrive.expect_tx.shared.b64 _, [%0], %1;"
                 :: "r"(m), "r"((uint32_t)(XB + TB)) : "memory");
    asm volatile("cp.async.bulk.shared::cta.global.mbarrier::complete_tx::bytes [%0], [%1], %2, [%3];"
                 :: "r"(xdst), "l"(xsrc), "r"((uint32_t)XB), "r"(m) : "memory");
    asm volatile("cp.async.bulk.shared::cta.global.mbarrier::complete_tx::bytes [%0], [%1], %2, [%3];"
                 :: "r"(tdst), "l"(tsrc), "r"((uint32_t)TB), "r"(m) : "memory");
}
__device__ __forceinline__ void mbar_wait(uint32_t m, int phase) {
    asm volatile(
        "{\n\t"
        ".reg .pred P;\n\t"
        "WL%=:\n\t"
        "mbarrier.try_wait.parity.acquire.cta.shared::cta.b64 P, [%0], %1, 0x989680;\n\t"
        "@!P bra WL%=;\n\t"
        "}"
        :: "r"(m), "r"((uint32_t)phase) : "memory");
}
__device__ __forceinline__ void sbar(int st) {
    asm volatile("bar.sync %0, %1;" :: "r"(st + 1), "r"(256) : "memory");
}

__global__ __launch_bounds__(NT) void mvke_main(
    const float* __restrict__ x, const float* __restrict__ tag,
    const float* __restrict__ fc1_b,
    float* __restrict__ out)
{
    extern __shared__ float sm[];

    const int tid  = threadIdx.x;
    const int st   = tid >> 8;       // stream 0/1 within CTA
    const int l    = tid & 255;      // thread id within stream
    const int w    = l >> 5;
    const int lane = l & 31;
    const int g    = (l >> 7) & 1;   // split-K half within stream
    const int idx  = l & 127;
    const float scale = 0.1f;                 // 1/sqrt(DK)
    const float PAD   = -4294967296.0f;       // float32(-(2^32)+1)

    // shared (both streams)
    float*  w2s  = sm + OW2;   float4* w2s4 = (float4*)w2s;
    float*  w3s  = sm + OW3;   float4* w3s4 = (float4*)w3s;
    float*  cs   = sm + OC;
    float*  c2s  = sm + OC2;
    // per-stream
    float*  ps   = sm + PSBASE + st * SS;
    float*  xs   = ps + PX;    float4* xs4 = (float4*)xs;
    float*  ys   = ps + PYS;   float4* ys4 = (float4*)ys;
    float*  wB   = ps + PWB;   float4* wB4 = (float4*)wB;
    float*  pb   = ps + PPB;
    float*  sas0 = ps + PSAS0;
    float*  sas1 = ps + PSAS1;
    float*  sbuf = ps + PSB;
    const uint32_t mb  = smem_u32(ps + PMB);
    const uint32_t xd  = smem_u32(xs);
    const uint32_t td0 = smem_u32(ps + PT0);
    const uint32_t td1 = smem_u32(ps + PT1);

    for (int i = tid; i < V_ * E_; i += NT) {
        w2s[i] = g_w2[i];
        w3s[i] = g_w3[i];
    }
    if (tid < V_) { cs[tid] = g_c[tid]; c2s[tid] = g_c2[tid]; }
    if (l == 0) mbar_init(mb);
    __syncthreads();

    const int NS = gridDim.x * 2;    // total streams
    int b = blockIdx.x * 2 + st;
    if (b >= B_) return;

    if (l == 0)
        issue_batch(mb, xd, td0, x + (size_t)b * (S_ * E_), tag + (size_t)b * (T_ * E_));

    int ph = 0, cur = 0;

    for (; b < B_; b += NS) {
        mbar_wait(mb, ph); ph ^= 1;
        const float4* tg4 = (const float4*)(ps + (cur ? PT1 : PT0));

        // ---- Phase A: raw m1 halves. thread-per-s, 3 v-accums, float4 over e (smem).
        if (idx < S_) {
            const int s = idx;
            const int q0 = g ? 13 : 0, q1 = g ? 25 : 13;
            const float4* xr = xs4 + s * 25;
            float a0 = 0.f, a1 = 0.f, a2 = 0.f, sa = 0.f;
            #pragma unroll 4
            for (int q = q0; q < q1; q++) {
                float4 xq = xr[q];
                float4 w0 = w2s4[q];
                float4 w1 = w2s4[25 + q];
                float4 w2q = w2s4[50 + q];
                a0 += dot4(xq, w0);
                a1 += dot4(xq, w1);
                a2 += dot4(xq, w2q);
                sa += fabsf(xq.x) + fabsf(xq.y) + fabsf(xq.z) + fabsf(xq.w);
            }
            if (!g) { wB[s] = a0; wB[100 + s] = a1; wB[200 + s] = a2; sas0[s] = sa; }
            else    { pb[s] = a0; pb[100 + s] = a1; pb[200 + s] = a2; sas1[s] = sa; }
        }
        sbar(st);

        // ---- Phase B: combine halves + mask + softmax over S per v (warp v)
        if (w < V_) {
            const int v = w;
            float vals[4];
            float mx = -3.4e38f;
            #pragma unroll
            for (int i = 0; i < 4; i++) {
                int s = lane + 32 * i;
                if (s < S_) {
                    float raw = wB[v * 100 + s] + pb[v * 100 + s];
                    bool msk = (sas0[s] + sas1[s]) == 0.0f;
                    vals[i] = msk ? PAD : scale * (raw + cs[v]);
                } else vals[i] = -3.4e38f;
                mx = fmaxf(mx, vals[i]);
            }
            #pragma unroll
            for (int off = 16; off; off >>= 1)
                mx = fmaxf(mx, __shfl_xor_sync(0xffffffffu, mx, off));
            float sum = 0.f;
            #pragma unroll
            for (int i = 0; i < 4; i++) {
                int s = lane + 32 * i;
                vals[i] = expf(vals[i] - mx);
                if (s < S_) sum += vals[i];
            }
            #pragma unroll
            for (int off = 16; off; off >>= 1)
                sum += __shfl_xor_sync(0xffffffffu, sum, off);
            float inv = 1.0f / sum;
            #pragma unroll
            for (int i = 0; i < 4; i++) {
                int s = lane + 32 * i;
                if (s < S_) wB[v * 100 + s] = vals[i] * inv;   // final sm1
            }
        }
        sbar(st);

        // ---- Phase C: ys halves. thread-per-e, 3 v-accums, float4 over s.
        if (idx < E_) {
            const int e = idx;
            const int q0 = g ? 13 : 0, q1 = g ? 25 : 13;
            float a0 = 0.f, a1 = 0.f, a2 = 0.f;
            #pragma unroll 4
            for (int q = q0; q < q1; q++) {
                float4 p0 = wB4[q];
                float4 p1 = wB4[25 + q];
                float4 p2 = wB4[50 + q];
                const float* xc = xs + (4 * q) * E_ + e;
                float x0 = xc[0];
                float x1 = xc[E_];
                float x2 = xc[2 * E_];
                float x3 = xc[3 * E_];
                a0 += p0.x * x0 + p0.y * x1 + p0.z * x2 + p0.w * x3;
                a1 += p1.x * x0 + p1.y * x1 + p1.z * x2 + p1.w * x3;
                a2 += p2.x * x0 + p2.y * x1 + p2.z * x2 + p2.w * x3;
            }
            if (!g) { ys[e] = a0; ys[100 + e] = a1; ys[200 + e] = a2; }
            else    { pb[e] = a0; pb[100 + e] = a1; pb[200 + e] = a2; }
        }
        sbar(st);   // xs fully consumed for this batch

        // prefetch next batch's x (+ tag into the other buffer); overlaps D/E/F
        {
            const int nb = b + NS;
            if (nb < B_ && l == 0)
                issue_batch(mb, xd, cur ? td0 : td1,
                            x + (size_t)nb * (S_ * E_), tag + (size_t)nb * (T_ * E_));
        }
        for (int i = l; i < V_ * E_; i += 256) ys[i] += pb[i];
        sbar(st);

        // ---- Phase D: ws1 halves. thread-per-i, float4 over e, coalesced L1/L2-hot fc1T.
        if (idx < E_) {
            const int i = idx;
            const int q0 = g ? 13 : 0, q1 = g ? 25 : 13;
            float a0 = 0.f, a1 = 0.f, a2 = 0.f;
            #pragma unroll 4
            for (int q = q0; q < q1; q++) {
                float4 y0 = ys4[q];
                float4 y1 = ys4[25 + q];
                float4 y2 = ys4[50 + q];
                const float* fp = g_fc1T + (4 * q) * E_ + i;
                float f0 = fp[0];
                float f1 = fp[E_];
                float f2 = fp[2 * E_];
                float f3 = fp[3 * E_];
                a0 += f0 * y0.x + f1 * y0.y + f2 * y0.z + f3 * y0.w;
                a1 += f0 * y1.x + f1 * y1.y + f2 * y1.z + f3 * y1.w;
                a2 += f0 * y2.x + f1 * y2.y + f2 * y2.z + f3 * y2.w;
            }
            if (!g) { wB[i] = a0; wB[100 + i] = a1; wB[200 + i] = a2; }
            else    { pb[i] = a0; pb[100 + i] = a1; pb[200 + i] = a2; }
        }
        sbar(st);
        for (int i = l; i < V_ * E_; i += 256)
            wB[i] = wB[i] + pb[i] + fc1_b[i % E_];   // final ws1
        sbar(st);

        // ---- Phase E: m2[t][v], d[t][v]; thread-per-(t,v), float4 over e (smem only)
        if (l < T_ * V_) {
            const int t = l / V_, v = l % V_;
            float am = 0.f, ad = 0.f;
            #pragma unroll 5
            for (int i = 0; i < 25; i++) {
                float4 tq = tg4[t * 25 + i];
                float4 wq = w3s4[v * 25 + i];
                float4 uq = wB4[v * 25 + i];
                am += dot4(tq, wq);
                ad += dot4(tq, uq);
            }
            sbuf[l]      = scale * (am + c2s[v]);  // m2
            sbuf[30 + l] = ad;                     // d
        }
        sbar(st);

        // ---- Phase F: softmax over T per v, then out
        if (l < V_) {
            const int v = l;
            float mx = sbuf[v];
            #pragma unroll
            for (int t = 1; t < T_; t++) mx = fmaxf(mx, sbuf[t * V_ + v]);
            float ev[T_];
            float sum = 0.f;
            #pragma unroll
            for (int t = 0; t < T_; t++) { ev[t] = expf(sbuf[t * V_ + v] - mx); sum += ev[t]; }
            float inv = 1.0f / sum;
            #pragma unroll
            for (int t = 0; t < T_; t++) sbuf[t * V_ + v] = ev[t] * inv;
        }
        sbar(st);
        if (l < T_) {
            const int t = l;
            out[(size_t)b * T_ + t] =
                sbuf[t * V_ + 0] * sbuf[30 + t * V_ + 0] +
                sbuf[t * V_ + 1] * sbuf[30 + t * V_ + 1] +
                sbuf[t * V_ + 2] * sbuf[30 + t * V_ + 2];
        }
        sbar(st);   // sbuf safe before next E; wB safe before next A
        cur ^= 1;
    }
}

extern "C" void kernel_launch(void* const* d_in, const int* in_sizes, int n_in,
                              void* d_out, int out_size)
{
    const float* x     = (const float*)d_in[0];
    const float* tag   = (const float*)d_in[1];
    const float* vk    = (const float*)d_in[2];
    const float* fc1_w = (const float*)d_in[3];
    const float* fc1_b = (const float*)d_in[4];
    const float* fc2_w = (const float*)d_in[5];
    const float* fc2_b = (const float*)d_in[6];
    const float* fc3_w = (const float*)d_in[7];
    const float* fc3_b = (const float*)d_in[8];
    const float* fc4_w = (const float*)d_in[9];
    const float* fc4_b = (const float*)d_in[10];
    float* out = (float*)d_out;

    cudaFuncSetAttribute(mvke_main, cudaFuncAttributeMaxDynamicSharedMemorySize, SMEM_BYTES);

    int sms = 148;
    cudaDeviceGetAttribute(&sms, cudaDevAttrMultiProcessorCount, 0);
    int grid = 2 * sms;

    mvke_pre<<<1, 384>>>(vk, fc1_w, fc1_b, fc2_w, fc2_b, fc3_w, fc3_b, fc4_w, fc4_b);
    mvke_main<<<grid, NT, SMEM_BYTES>>>(x, tag, fc1_b, out);
}